// round 1
// baseline (speedup 1.0000x reference)
#include <cuda_runtime.h>
#include <math.h>

#define T1V 257
#define BATCH 512
#define SDV 128
#define ADV 32
#define HSV 512
#define SFV 256
#define R2 131072    // 256*512 rows
#define RALL 131584  // 257*512 rows

// ---------------- scratch (__device__ globals; no runtime allocation) ----------------
__device__ float g_feats[(size_t)T1V * BATCH * HSV];   // 257x512x512
__device__ float g_outs [(size_t)T1V * BATCH * SFV];   // 257x512x256
__device__ float g_pred [(size_t)256 * BATCH * SFV];   // 256x512x256
__device__ float g_hidA [(size_t)R2 * HSV];            // 131072x512
__device__ float g_hidB [(size_t)R2 * HSV];            // 131072x512
__device__ float g_h0   [2 * BATCH * SFV];
__device__ float g_h1   [2 * BATCH * SFV];
__device__ float g_c0   [BATCH * SFV];
__device__ float g_c1   [BATCH * SFV];
__device__ float g_pfl  [2048];
__device__ float g_pil  [512];

// ---------------- helpers ----------------
__device__ __forceinline__ float sigmoidf_(float x) { return 1.0f / (1.0f + expf(-x)); }

// ---------------- zero init for recurrent state ----------------
__global__ void zero_state_kernel() {
    int i = blockIdx.x * blockDim.x + threadIdx.x;  // 131072 total
    g_h0[i] = 0.f;
    g_h1[i] = 0.f;
    g_c0[i] = 0.f;
    g_c1[i] = 0.f;
}

// ---------------- generic SGEMM: C = act(A @ W^T + bias) ----------------
// A row r = concat(A1[r, 0:K1], A2[r, 0:K-K1]); W is [N,K] row-major.
// Tiles: 128x128, KC=16, 256 threads, 8x8 microtile.
#define KC 16
template <int ACT>
__global__ __launch_bounds__(256) void gemm_kernel(
    const float* __restrict__ A1, int K1,
    const float* __restrict__ A2,
    const float* __restrict__ W,
    const float* __restrict__ bias,
    float* __restrict__ C,
    int M, int N, int K)
{
    __shared__ float as_[KC][132];
    __shared__ float bs_[KC][132];
    const int m0 = blockIdx.x * 128;
    const int n0 = blockIdx.y * 128;
    const int tid = threadIdx.x;
    const int mi = tid >> 4;   // 0..15
    const int ni = tid & 15;   // 0..15
    const int lrow = tid >> 2;        // 0..63
    const int lk = (tid & 3) * 4;     // 0,4,8,12

    float acc[8][8];
#pragma unroll
    for (int i = 0; i < 8; i++)
#pragma unroll
        for (int j = 0; j < 8; j++) acc[i][j] = 0.f;

    for (int kc = 0; kc < K; kc += KC) {
        const float* Asrc;
        int Ak, koff;
        if (kc < K1) { Asrc = A1; Ak = K1; koff = kc; }
        else         { Asrc = A2; Ak = K - K1; koff = kc - K1; }
#pragma unroll
        for (int r = 0; r < 2; r++) {
            int row = lrow + r * 64;
            float4 v = *(const float4*)(Asrc + (size_t)(m0 + row) * Ak + koff + lk);
            as_[lk + 0][row] = v.x; as_[lk + 1][row] = v.y;
            as_[lk + 2][row] = v.z; as_[lk + 3][row] = v.w;
            float4 w = *(const float4*)(W + (size_t)(n0 + row) * K + kc + lk);
            bs_[lk + 0][row] = w.x; bs_[lk + 1][row] = w.y;
            bs_[lk + 2][row] = w.z; bs_[lk + 3][row] = w.w;
        }
        __syncthreads();
#pragma unroll
        for (int k = 0; k < KC; k++) {
            float4 a0 = *(const float4*)&as_[k][mi * 8];
            float4 a1 = *(const float4*)&as_[k][mi * 8 + 4];
            float a[8] = {a0.x, a0.y, a0.z, a0.w, a1.x, a1.y, a1.z, a1.w};
            float b[8];
#pragma unroll
            for (int j = 0; j < 8; j++) b[j] = bs_[k][ni + j * 16];
#pragma unroll
            for (int i = 0; i < 8; i++)
#pragma unroll
                for (int j = 0; j < 8; j++) acc[i][j] += a[i] * b[j];
        }
        __syncthreads();
    }
#pragma unroll
    for (int i = 0; i < 8; i++) {
        int row = m0 + mi * 8 + i;
#pragma unroll
        for (int j = 0; j < 8; j++) {
            int col = n0 + ni + j * 16;
            float v = acc[i][j] + bias[col];
            if (ACT == 1) v = fmaxf(v, 0.f);
            C[(size_t)row * N + col] = v;
        }
    }
}

// ---------------- one LSTM layer step ----------------
// Tile: 64 batch x 16 units (64 gate rows). grid (8,16), 256 threads.
// Thread: 4 batches x 1 unit x 4 gates.
__global__ __launch_bounds__(256) void lstm_step_kernel(
    const float* __restrict__ x, int Kx,
    const float* __restrict__ h_in,
    float* __restrict__ h_out,
    float* __restrict__ c,
    const float* __restrict__ Wih,   // [1024, Kx]
    const float* __restrict__ Whh,   // [1024, 256]
    const float* __restrict__ bih,
    const float* __restrict__ bhh,
    const int* __restrict__ done,    // [512]
    float* __restrict__ outp)        // optional copy of h_out
{
    __shared__ float as_[KC][76];
    __shared__ float ws_[KC][76];
    __shared__ float msk[64];

    const int b0 = blockIdx.x * 64;
    const int u0 = blockIdx.y * 16;
    const int tid = threadIdx.x;
    const int ui = tid & 15;
    const int bq = tid >> 4;          // 0..15
    const int lrow = tid >> 2;        // 0..63
    const int lk = (tid & 3) * 4;

    if (tid < 64) msk[tid] = 1.f - (float)done[b0 + tid];

    float acc[4][4];
#pragma unroll
    for (int i = 0; i < 4; i++)
#pragma unroll
        for (int g = 0; g < 4; g++) acc[i][g] = 0.f;

    const int wrow = ((lrow >> 4) << 8) + u0 + (lrow & 15);  // gate*256 + unit

    // phase 1: x @ Wih^T
    {
        const float* xr = x + (size_t)(b0 + lrow) * Kx;
        const float* wr = Wih + (size_t)wrow * Kx;
        for (int kc = 0; kc < Kx; kc += KC) {
            float4 xv = *(const float4*)(xr + kc + lk);
            float4 wv = *(const float4*)(wr + kc + lk);
            as_[lk + 0][lrow] = xv.x; as_[lk + 1][lrow] = xv.y;
            as_[lk + 2][lrow] = xv.z; as_[lk + 3][lrow] = xv.w;
            ws_[lk + 0][lrow] = wv.x; ws_[lk + 1][lrow] = wv.y;
            ws_[lk + 2][lrow] = wv.z; ws_[lk + 3][lrow] = wv.w;
            __syncthreads();
#pragma unroll
            for (int k = 0; k < KC; k++) {
                float4 a4 = *(const float4*)&as_[k][bq << 2];
                float w0 = ws_[k][ui], w1 = ws_[k][16 + ui];
                float w2 = ws_[k][32 + ui], w3 = ws_[k][48 + ui];
                acc[0][0] += a4.x * w0; acc[0][1] += a4.x * w1; acc[0][2] += a4.x * w2; acc[0][3] += a4.x * w3;
                acc[1][0] += a4.y * w0; acc[1][1] += a4.y * w1; acc[1][2] += a4.y * w2; acc[1][3] += a4.y * w3;
                acc[2][0] += a4.z * w0; acc[2][1] += a4.z * w1; acc[2][2] += a4.z * w2; acc[2][3] += a4.z * w3;
                acc[3][0] += a4.w * w0; acc[3][1] += a4.w * w1; acc[3][2] += a4.w * w2; acc[3][3] += a4.w * w3;
            }
            __syncthreads();
        }
    }
    // phase 2: (h_in * mask) @ Whh^T
    {
        const float* hr = h_in + (size_t)(b0 + lrow) * SFV;
        const float* wr = Whh + (size_t)wrow * SFV;
        const float mrow = msk[lrow];
        for (int kc = 0; kc < SFV; kc += KC) {
            float4 hv = *(const float4*)(hr + kc + lk);
            float4 wv = *(const float4*)(wr + kc + lk);
            as_[lk + 0][lrow] = hv.x * mrow; as_[lk + 1][lrow] = hv.y * mrow;
            as_[lk + 2][lrow] = hv.z * mrow; as_[lk + 3][lrow] = hv.w * mrow;
            ws_[lk + 0][lrow] = wv.x; ws_[lk + 1][lrow] = wv.y;
            ws_[lk + 2][lrow] = wv.z; ws_[lk + 3][lrow] = wv.w;
            __syncthreads();
#pragma unroll
            for (int k = 0; k < KC; k++) {
                float4 a4 = *(const float4*)&as_[k][bq << 2];
                float w0 = ws_[k][ui], w1 = ws_[k][16 + ui];
                float w2 = ws_[k][32 + ui], w3 = ws_[k][48 + ui];
                acc[0][0] += a4.x * w0; acc[0][1] += a4.x * w1; acc[0][2] += a4.x * w2; acc[0][3] += a4.x * w3;
                acc[1][0] += a4.y * w0; acc[1][1] += a4.y * w1; acc[1][2] += a4.y * w2; acc[1][3] += a4.y * w3;
                acc[2][0] += a4.z * w0; acc[2][1] += a4.z * w1; acc[2][2] += a4.z * w2; acc[2][3] += a4.z * w3;
                acc[3][0] += a4.w * w0; acc[3][1] += a4.w * w1; acc[3][2] += a4.w * w2; acc[3][3] += a4.w * w3;
            }
            __syncthreads();
        }
    }
    // epilogue: gates -> cell update
    const int u = u0 + ui;
    float bsum[4];
#pragma unroll
    for (int g = 0; g < 4; g++) bsum[g] = bih[g * SFV + u] + bhh[g * SFV + u];
#pragma unroll
    for (int i = 0; i < 4; i++) {
        int b = b0 + (bq << 2) + i;
        float ig = sigmoidf_(acc[i][0] + bsum[0]);
        float fg = sigmoidf_(acc[i][1] + bsum[1]);
        float gg = tanhf(acc[i][2] + bsum[2]);
        float og = sigmoidf_(acc[i][3] + bsum[3]);
        float cold = c[(size_t)b * SFV + u] * msk[b - b0];
        float c2 = fg * cold + ig * gg;
        float h2 = og * tanhf(c2);
        c[(size_t)b * SFV + u] = c2;
        h_out[(size_t)b * SFV + u] = h2;
        if (outp) outp[(size_t)b * SFV + u] = h2;
    }
}

// ---------------- forward loss + intrinsic reward ----------------
// row r = t*512+b (t in 0..255). next_sf row = r + 512 of outs.
__global__ void floss_kernel(const float* __restrict__ pred, const float* __restrict__ outs,
                             float* __restrict__ intr, float* __restrict__ pfl)
{
    const int w = threadIdx.x >> 5, lane = threadIdx.x & 31;
    const int r0 = blockIdx.x * 64;
    __shared__ float sred[8];
    float wacc = 0.f;
    for (int p = 0; p < 8; p++) {
        int r = r0 + p * 8 + w;
        const float4* pp = (const float4*)(pred + (size_t)r * SFV) + lane * 2;
        const float4* np = (const float4*)(outs + (size_t)(r + BATCH) * SFV) + lane * 2;
        float4 p0 = pp[0], p1 = pp[1], n0 = np[0], n1 = np[1];
        float d0 = p0.x - n0.x, d1 = p0.y - n0.y, d2 = p0.z - n0.z, d3 = p0.w - n0.w;
        float d4 = p1.x - n1.x, d5 = p1.y - n1.y, d6 = p1.z - n1.z, d7 = p1.w - n1.w;
        float s = d0 * d0 + d1 * d1 + d2 * d2 + d3 * d3 + d4 * d4 + d5 * d5 + d6 * d6 + d7 * d7;
#pragma unroll
        for (int o = 16; o; o >>= 1) s += __shfl_xor_sync(0xffffffffu, s, o);
        if (lane == 0) { intr[r] = s; wacc += s; }
    }
    if (lane == 0) sred[w] = wacc;
    __syncthreads();
    if (threadIdx.x == 0) {
        float t = 0.f;
        for (int i = 0; i < 8; i++) t += sred[i];
        pfl[blockIdx.x] = t;
    }
}

// ---------------- inverse head: mu/std + NLL partials ----------------
__global__ void inv_kernel(const float* __restrict__ hm, const float* __restrict__ hs,
                           const float* __restrict__ Wm2, const float* __restrict__ bm2,
                           const float* __restrict__ Ws2, const float* __restrict__ bs2,
                           const float* __restrict__ act, float* __restrict__ pil)
{
    extern __shared__ float sh[];
    float* wm = sh;              // [512*32] (k-major, d contiguous)
    float* ws2s = sh + 16384;
    float* bm = sh + 32768;
    float* bs = sh + 32800;
    float* red = sh + 32832;     // 8
    const int tid = threadIdx.x;
    for (int idx = tid; idx < 16384; idx += 256) {
        int d = idx & 31, k = idx >> 5;
        wm[idx] = Wm2[(size_t)d * HSV + k];
        ws2s[idx] = Ws2[(size_t)d * HSV + k];
    }
    if (tid < 32) { bm[tid] = bm2[tid]; bs[tid] = bs2[tid]; }
    __syncthreads();

    const int w = tid >> 5, lane = tid & 31;
    const int r0 = blockIdx.x * 256;
    float ilacc = 0.f;
    for (int p = 0; p < 32; p++) {
        int r = r0 + p * 8 + w;
        const float4* h4m = (const float4*)(hm + (size_t)r * HSV);
        const float4* h4s = (const float4*)(hs + (size_t)r * HSV);
        float am = 0.f, as2 = 0.f;
#pragma unroll 4
        for (int k4 = 0; k4 < 128; k4++) {
            float4 a = h4m[k4];
            float4 b = h4s[k4];
            int kb = k4 * 128 + lane;
            am  += a.x * wm[kb] + a.y * wm[kb + 32] + a.z * wm[kb + 64] + a.w * wm[kb + 96];
            as2 += b.x * ws2s[kb] + b.y * ws2s[kb + 32] + b.z * ws2s[kb + 64] + b.w * ws2s[kb + 96];
        }
        float mu = tanhf(am + bm[lane]);
        float sv = as2 + bs[lane];
        float sd = fmaxf(sv, 0.f) + log1pf(expf(-fabsf(sv)));  // softplus
        float a_ = act[(size_t)r * ADV + lane];
        float z = (a_ - mu) / sd;
        ilacc += 0.5f * z * z + logf(sd) + 0.91893853320467274f;
    }
#pragma unroll
    for (int o = 16; o; o >>= 1) ilacc += __shfl_xor_sync(0xffffffffu, ilacc, o);
    if (lane == 0) red[w] = ilacc;
    __syncthreads();
    if (tid == 0) {
        float t = 0.f;
        for (int i = 0; i < 8; i++) t += red[i];
        pil[blockIdx.x] = t;
    }
}

// ---------------- final scalar reduce ----------------
__global__ void final_reduce_kernel(const float* __restrict__ pfl, const float* __restrict__ pil,
                                    float* __restrict__ out)
{
    __shared__ float s1[256], s2[256];
    int tid = threadIdx.x;
    float a = 0.f, b = 0.f;
    for (int i = tid; i < 2048; i += 256) a += pfl[i];
    for (int i = tid; i < 512; i += 256) b += pil[i];
    s1[tid] = a; s2[tid] = b;
    __syncthreads();
    for (int st = 128; st; st >>= 1) {
        if (tid < st) { s1[tid] += s1[tid + st]; s2[tid] += s2[tid + st]; }
        __syncthreads();
    }
    if (tid == 0) {
        out[0] = s1[0] / 33554432.f;   // mean over 256*512*256
        out[1] = s2[0] / 4194304.f;    // mean over 256*512*32
    }
}

// ---------------- hidden copy ----------------
__global__ void copy_hidden_kernel(const float* __restrict__ h0f, const float* __restrict__ h1f,
                                   const float* __restrict__ c0, const float* __restrict__ c1,
                                   float* __restrict__ dst)
{
    int i = blockIdx.x * blockDim.x + threadIdx.x;  // 131072
    dst[i] = h0f[i];
    dst[131072 + i] = h1f[i];
    dst[262144 + i] = c0[i];
    dst[393216 + i] = c1[i];
}

// ---------------- host orchestration ----------------
extern "C" void kernel_launch(void* const* d_in, const int* in_sizes, int n_in,
                              void* d_out, int out_size)
{
    (void)in_sizes; (void)n_in; (void)out_size;
    const float* states = (const float*)d_in[0];
    const float* action = (const float*)d_in[1];
    const int*   dones  = (const int*)d_in[2];
    const float* Wfe = (const float*)d_in[3];
    const float* bfe = (const float*)d_in[4];
    const float* Wih0 = (const float*)d_in[5];
    const float* Whh0 = (const float*)d_in[6];
    const float* bih0 = (const float*)d_in[7];
    const float* bhh0 = (const float*)d_in[8];
    const float* Wih1 = (const float*)d_in[9];
    const float* Whh1 = (const float*)d_in[10];
    const float* bih1 = (const float*)d_in[11];
    const float* bhh1 = (const float*)d_in[12];
    const float* Wf1 = (const float*)d_in[13];
    const float* bf1 = (const float*)d_in[14];
    const float* Wf2 = (const float*)d_in[15];
    const float* bf2 = (const float*)d_in[16];
    const float* Wm1 = (const float*)d_in[17];
    const float* bm1 = (const float*)d_in[18];
    const float* Wm2 = (const float*)d_in[19];
    const float* bm2 = (const float*)d_in[20];
    const float* Ws1 = (const float*)d_in[21];
    const float* bs1 = (const float*)d_in[22];
    const float* Ws2 = (const float*)d_in[23];
    const float* bs2 = (const float*)d_in[24];
    float* out = (float*)d_out;

    float *feats, *outs, *pred, *hidA, *hidB, *h0b, *h1b, *c0, *c1, *pfl, *pil;
    cudaGetSymbolAddress((void**)&feats, g_feats);
    cudaGetSymbolAddress((void**)&outs, g_outs);
    cudaGetSymbolAddress((void**)&pred, g_pred);
    cudaGetSymbolAddress((void**)&hidA, g_hidA);
    cudaGetSymbolAddress((void**)&hidB, g_hidB);
    cudaGetSymbolAddress((void**)&h0b, g_h0);
    cudaGetSymbolAddress((void**)&h1b, g_h1);
    cudaGetSymbolAddress((void**)&c0, g_c0);
    cudaGetSymbolAddress((void**)&c1, g_c1);
    cudaGetSymbolAddress((void**)&pfl, g_pfl);
    cudaGetSymbolAddress((void**)&pil, g_pil);

    cudaFuncSetAttribute(inv_kernel, cudaFuncAttributeMaxDynamicSharedMemorySize, 32840 * 4);

    // zero recurrent state
    zero_state_kernel<<<256, 512>>>();

    // feature encoder: feats = relu(states @ Wfe^T + bfe)
    gemm_kernel<1><<<dim3(RALL / 128, HSV / 128), 256>>>(
        states, SDV, nullptr, Wfe, bfe, feats, RALL, HSV, SDV);

    // LSTM scan
    float* h0p[2] = {h0b, h0b + BATCH * SFV};
    float* h1p[2] = {h1b, h1b + BATCH * SFV};
    dim3 lgrid(8, 16);
    for (int t = 0; t < T1V; t++) {
        int pp = t & 1;
        lstm_step_kernel<<<lgrid, 256>>>(
            feats + (size_t)t * BATCH * HSV, HSV,
            h0p[pp], h0p[1 - pp], c0,
            Wih0, Whh0, bih0, bhh0,
            dones + (size_t)t * BATCH, nullptr);
        lstm_step_kernel<<<lgrid, 256>>>(
            h0p[1 - pp], SFV,
            h1p[pp], h1p[1 - pp], c1,
            Wih1, Whh1, bih1, bhh1,
            dones + (size_t)t * BATCH,
            outs + (size_t)t * BATCH * SFV);
    }

    // forward model: hidA = relu([sf, action] @ Wf1^T + bf1); pred = hidA @ Wf2^T + bf2
    gemm_kernel<1><<<dim3(R2 / 128, HSV / 128), 256>>>(
        outs, SFV, action, Wf1, bf1, hidA, R2, HSV, SFV + ADV);
    gemm_kernel<0><<<dim3(R2 / 128, SFV / 128), 256>>>(
        hidA, HSV, nullptr, Wf2, bf2, pred, R2, SFV, HSV);

    // forward loss + intrinsic reward (out[2 .. 2+131072))
    floss_kernel<<<2048, 256>>>(pred, outs, out + 2, pfl);

    // inverse model hiddens: hidA = relu([sf,pred]@Wm1^T+bm1), hidB = relu([sf,pred]@Ws1^T+bs1)
    gemm_kernel<1><<<dim3(R2 / 128, HSV / 128), 256>>>(
        outs, SFV, pred, Wm1, bm1, hidA, R2, HSV, 2 * SFV);
    gemm_kernel<1><<<dim3(R2 / 128, HSV / 128), 256>>>(
        outs, SFV, pred, Ws1, bs1, hidB, R2, HSV, 2 * SFV);

    // mu/std + inverse-loss partials
    inv_kernel<<<512, 256, 32840 * 4>>>(hidA, hidB, Wm2, bm2, Ws2, bs2, action, pil);

    // scalars
    final_reduce_kernel<<<1, 256>>>(pfl, pil, out);

    // hidden = [h0_T, h1_T, c0_T, c1_T]  (final h in ping-pong buffer 1 after 257 steps)
    copy_hidden_kernel<<<256, 512>>>(h0p[1], h1p[1], c0, c1, out + 2 + 131072);
}